// round 4
// baseline (speedup 1.0000x reference)
#include <cuda_runtime.h>

// Problem constants (fixed by the reference)
#define B       32
#define N       2048
#define OUTD    100
#define JSPLITS 16
#define JCHUNK  (N / JSPLITS)        // 128
#define BPG     4                    // batch rows per block
#define BGROUPS (B / BPG)            // 8
#define GRID1   (JSPLITS * BGROUPS)  // 128 blocks
#define NT      512
#define NW      16
#define J_PER_WARP (JCHUNK / NW)     // 8

// Reference: out[b,o] = sum_j rem[b,j] W[j,o],
//   rem[b,j] = (q - (N*c + S_b))^2, c = (int)q, S_b = sum_j c  (exact ints < 2^24)
// Expansion with e = q - N*c (block-local, no S needed):
//   out[b,o] = A - 2*S_b*B + S_b^2*C,
//   A = sum e^2 W, B = sum e W, C = sum_j W[j,o].
// All sums fixed-order -> deterministic. No atomics, no fences.

__device__ float g_A [JSPLITS][B][OUTD];
__device__ float g_Bv[JSPLITS][B][OUTD];
__device__ float g_Cv[JSPLITS][OUTD];
__device__ int   g_S [JSPLITS][B];

__global__ __launch_bounds__(NT, 1)
void rowstat_partials_kernel(const float* __restrict__ q,
                             const float* __restrict__ W)
{
    __shared__ float2 ep[BPG][JCHUNK];          // (e, e*e)  4 KB
    __shared__ float  part[NW][BPG * OUTD];     // 25.6 KB (A, then reused for B)
    __shared__ float  cpart[NW][OUTD];          // 6.4 KB
    __shared__ int    qsum[NW];

    const int tid  = threadIdx.x;
    const int wid  = tid >> 5;
    const int lane = tid & 31;
    const int s    = blockIdx.x & (JSPLITS - 1);
    const int bg   = blockIdx.x >> 4;
    const int j0   = s * JCHUNK;

    // ---- Prefetch W slice into registers (independent of q path) ----
    const int g  = lane;                 // g<25 owns outputs 4g..4g+3
    const int jw = wid * J_PER_WARP;
    float4 w4[J_PER_WARP];
    if (g < 25) {
        const float* Wg = W + (size_t)(j0 + jw) * OUTD + g * 4;
        #pragma unroll
        for (int jj = 0; jj < J_PER_WARP; ++jj)
            w4[jj] = *reinterpret_cast<const float4*>(Wg + jj * OUTD);
    }

    // ---- Load q chunk (1 float/thread), compute e, e^2, partial int sums ----
    {
        const int r   = tid >> 7;        // row in group (0..3), warps 4r..4r+3
        const int col = tid & 127;
        float qv = q[(size_t)(bg * BPG + r) * N + j0 + col];
        int   c  = (int)qv;              // trunc toward zero == astype(int32)
        float e  = qv - (float)(N * c);  // N*c exact int < 2^24
        ep[r][col] = make_float2(e, e * e);

        int ss = c;
        #pragma unroll
        for (int o = 16; o > 0; o >>= 1) ss += __shfl_xor_sync(0xFFFFFFFFu, ss, o);
        if (lane == 0) qsum[wid] = ss;
    }
    __syncthreads();

    if (tid < BPG)
        g_S[s][bg * BPG + tid] =
            qsum[4*tid] + qsum[4*tid+1] + qsum[4*tid+2] + qsum[4*tid+3];

    // ---- GEMV: A, B (and C for bg==0) on registers + smem broadcast ----
    float aA[BPG][4], aB[BPG][4], aC[4];
    if (g < 25) {
        #pragma unroll
        for (int rr = 0; rr < BPG; ++rr) {
            aA[rr][0]=aA[rr][1]=aA[rr][2]=aA[rr][3]=0.f;
            aB[rr][0]=aB[rr][1]=aB[rr][2]=aB[rr][3]=0.f;
        }
        aC[0]=aC[1]=aC[2]=aC[3]=0.f;

        #pragma unroll
        for (int jj = 0; jj < J_PER_WARP; ++jj) {
            const float4 w = w4[jj];
            if (bg == 0) { aC[0]+=w.x; aC[1]+=w.y; aC[2]+=w.z; aC[3]+=w.w; }
            #pragma unroll
            for (int rr = 0; rr < BPG; ++rr) {
                const float2 ev = ep[rr][jw + jj];   // (e, e^2) broadcast
                aA[rr][0]=fmaf(ev.y, w.x, aA[rr][0]);
                aA[rr][1]=fmaf(ev.y, w.y, aA[rr][1]);
                aA[rr][2]=fmaf(ev.y, w.z, aA[rr][2]);
                aA[rr][3]=fmaf(ev.y, w.w, aA[rr][3]);
                aB[rr][0]=fmaf(ev.x, w.x, aB[rr][0]);
                aB[rr][1]=fmaf(ev.x, w.y, aB[rr][1]);
                aB[rr][2]=fmaf(ev.x, w.z, aB[rr][2]);
                aB[rr][3]=fmaf(ev.x, w.w, aB[rr][3]);
            }
        }
        #pragma unroll
        for (int rr = 0; rr < BPG; ++rr)
            *reinterpret_cast<float4*>(&part[wid][rr * OUTD + g * 4]) =
                make_float4(aA[rr][0], aA[rr][1], aA[rr][2], aA[rr][3]);
        if (bg == 0)
            *reinterpret_cast<float4*>(&cpart[wid][g * 4]) =
                make_float4(aC[0], aC[1], aC[2], aC[3]);
    }
    __syncthreads();

    // ---- Reduce A across warps (threads 0..399); C by threads 400..499 ----
    if (tid < BPG * OUTD) {
        float ssum = 0.f;
        #pragma unroll
        for (int w = 0; w < NW; ++w) ssum += part[w][tid];
        const int rr = tid / OUTD;
        const int o  = tid - rr * OUTD;
        g_A[s][bg * BPG + rr][o] = ssum;
    } else if (bg == 0 && tid < BPG * OUTD + OUTD) {
        const int o = tid - BPG * OUTD;
        float ssum = 0.f;
        #pragma unroll
        for (int w = 0; w < NW; ++w) ssum += cpart[w][o];
        g_Cv[s][o] = ssum;
    }
    __syncthreads();

    // ---- Reuse part buffer for B ----
    if (g < 25) {
        #pragma unroll
        for (int rr = 0; rr < BPG; ++rr)
            *reinterpret_cast<float4*>(&part[wid][rr * OUTD + g * 4]) =
                make_float4(aB[rr][0], aB[rr][1], aB[rr][2], aB[rr][3]);
    }
    __syncthreads();

    if (tid < BPG * OUTD) {
        float ssum = 0.f;
        #pragma unroll
        for (int w = 0; w < NW; ++w) ssum += part[w][tid];
        const int rr = tid / OUTD;
        const int o  = tid - rr * OUTD;
        g_Bv[s][bg * BPG + rr][o] = ssum;
    }
}

__global__ __launch_bounds__(128, 8)
void rowstat_combine_kernel(float* __restrict__ out)
{
    const int b = blockIdx.x;            // 32 blocks
    const int o = threadIdx.x;           // 100 active of 128
    if (o >= OUTD) return;

    float A = 0.f, Bv = 0.f, C = 0.f;
    int   S = 0;
    #pragma unroll
    for (int sp = 0; sp < JSPLITS; ++sp) {
        A  += g_A [sp][b][o];
        Bv += g_Bv[sp][b][o];
        C  += g_Cv[sp][o];
        S  += g_S [sp][b];
    }
    const float Sf = (float)S;           // exact int
    out[b * OUTD + o] = fmaf(Sf * Sf, C, fmaf(-2.f * Sf, Bv, A));
}

extern "C" void kernel_launch(void* const* d_in, const int* in_sizes, int n_in,
                              void* d_out, int out_size)
{
    const float* q = (const float*)d_in[0];   // [32, 2048] f32
    const float* W = (const float*)d_in[1];   // [2048, 100] f32
    float* out = (float*)d_out;               // [32, 100] f32
    (void)in_sizes; (void)n_in; (void)out_size;

    rowstat_partials_kernel<<<GRID1, NT>>>(q, W);
    rowstat_combine_kernel<<<B, 128>>>(out);
}